// round 10
// baseline (speedup 1.0000x reference)
#include <cuda_runtime.h>
#include <cuda_fp16.h>
#include <cstdint>

// ---------------------------------------------------------------------------
// CrossAttention, fp16-operand / fp32-accum pipeline (m16n8k16 HMMA).
// GEMMs: BK=32, 3-stage cp.async (2-ahead prefetch), 64x64 warp tiles.
// Flash: 128-key double-buffered stages, one sync per 128 keys.
// b=4, n=2048, m=1024, qd=1024, cd=768, heads=8, dim_head=64, inner=512
// ---------------------------------------------------------------------------

#define B_     4
#define N_     2048
#define M_     1024
#define QD_    1024
#define CD_    768
#define H_     8
#define D_     64
#define INNER_ 512
#define KV_LD  1024
#define SCALE_ 0.125f   // 64^-0.5 (exact power of two)

// Scratch (device globals: allocation-free rule)
__device__ __align__(16) static __half g_xh[(size_t)B_ * N_ * QD_];
__device__ __align__(16) static __half g_ch[(size_t)B_ * M_ * CD_];
__device__ __align__(16) static __half g_wqt[(size_t)INNER_ * QD_];
__device__ __align__(16) static __half g_wkvt[(size_t)KV_LD * CD_];   // [Wk^T; Wv^T]
__device__ __align__(16) static __half g_wot[(size_t)QD_ * INNER_];
__device__ __align__(16) static __half g_q[(size_t)B_ * N_ * INNER_];
__device__ __align__(16) static __half g_kv[(size_t)B_ * M_ * KV_LD]; // K | V
__device__ __align__(16) static __half g_o[(size_t)B_ * N_ * INNER_];

__device__ __forceinline__ uint32_t smem_u32(const void* p) {
    return (uint32_t)__cvta_generic_to_shared(p);
}
__device__ __forceinline__ void cp16(uint32_t saddr, const void* g) {
    asm volatile("cp.async.cg.shared.global [%0], [%1], 16;\n" :: "r"(saddr), "l"(g));
}
__device__ __forceinline__ void ldsm4(uint32_t& r0, uint32_t& r1, uint32_t& r2,
                                      uint32_t& r3, uint32_t addr) {
    asm volatile("ldmatrix.sync.aligned.m8n8.x4.shared.b16 {%0,%1,%2,%3}, [%4];"
                 : "=r"(r0), "=r"(r1), "=r"(r2), "=r"(r3) : "r"(addr));
}
__device__ __forceinline__ void ldsm4t(uint32_t& r0, uint32_t& r1, uint32_t& r2,
                                       uint32_t& r3, uint32_t addr) {
    asm volatile("ldmatrix.sync.aligned.m8n8.x4.trans.shared.b16 {%0,%1,%2,%3}, [%4];"
                 : "=r"(r0), "=r"(r1), "=r"(r2), "=r"(r3) : "r"(addr));
}
__device__ __forceinline__ void mma_f16(float c[4], const uint32_t a[4],
                                        const uint32_t b[2]) {
    asm volatile(
        "mma.sync.aligned.m16n8k16.row.col.f32.f16.f16.f32 "
        "{%0,%1,%2,%3}, {%4,%5,%6,%7}, {%8,%9}, {%0,%1,%2,%3};\n"
        : "+f"(c[0]), "+f"(c[1]), "+f"(c[2]), "+f"(c[3])
        : "r"(a[0]), "r"(a[1]), "r"(a[2]), "r"(a[3]), "r"(b[0]), "r"(b[1]));
}
__device__ __forceinline__ uint32_t packh2(float lo, float hi) {
    __half2 h = __floats2half2_rn(lo, hi);
    return *reinterpret_cast<uint32_t*>(&h);
}

// ---------------------------------------------------------------------------
// Prep: fp16-round copies (x, ctx) and 4-way transpose+round (weights).
// ---------------------------------------------------------------------------
__global__ void __launch_bounds__(256) round_copy2h_k(
    const float4* __restrict__ a, uint2* __restrict__ ao, int n4a,
    const float4* __restrict__ b, uint2* __restrict__ bo, int n4b)
{
    int i = blockIdx.x * 256 + threadIdx.x;
    if (i < n4a) {
        float4 t = a[i];
        uint2 r; r.x = packh2(t.x, t.y); r.y = packh2(t.z, t.w);
        ao[i] = r;
    } else if (i < n4a + n4b) {
        int j = i - n4a;
        float4 t = b[j];
        uint2 r; r.x = packh2(t.x, t.y); r.y = packh2(t.z, t.w);
        bo[j] = r;
    }
}

__global__ void __launch_bounds__(256) transpose_round4h_k(
    const float* __restrict__ W0, __half* __restrict__ T0,
    const float* __restrict__ W1, __half* __restrict__ T1,
    const float* __restrict__ W2, __half* __restrict__ T2,
    const float* __restrict__ W3, __half* __restrict__ T3)
{
    const float* W; __half* Tt; int K, N;
    switch (blockIdx.z) {
        case 0:  W = W0; Tt = T0; K = QD_;    N = INNER_; break;
        case 1:  W = W1; Tt = T1; K = CD_;    N = INNER_; break;
        case 2:  W = W2; Tt = T2; K = CD_;    N = INNER_; break;
        default: W = W3; Tt = T3; K = INNER_; N = QD_;    break;
    }
    const int n0 = blockIdx.x * 32, k0 = blockIdx.y * 32;
    if (n0 >= N || k0 >= K) return;

    __shared__ float t[32][33];
    const int tx = threadIdx.x & 31, ty = threadIdx.x >> 5;
#pragma unroll
    for (int j = 0; j < 32; j += 8)
        t[ty + j][tx] = W[(long)(k0 + ty + j) * N + n0 + tx];
    __syncthreads();
#pragma unroll
    for (int j = 0; j < 32; j += 8)
        Tt[(long)(n0 + ty + j) * K + k0 + tx] = __float2half_rn(t[tx][ty + j]);
}

// ---------------------------------------------------------------------------
// fp16 GEMM core: C[128x128 tile] = A[M][K] * Bt[N][K]^T.
// 4 warps (64x64 each), BK=32 halfs, 3-stage cp.async (prefetch 2 ahead),
// one __syncthreads per chunk. Rows padded to 40 halfs (80B) -> LDSM granule
// 5r mod 8 covers all banks; rows 16B-aligned.
// ---------------------------------------------------------------------------
#define LDKH2   40
#define HSTG2_B ((128 + 128) * LDKH2 * 2)   // 20480 B per stage
#define GEMM_SMEM (3 * HSTG2_B)             // 61440 B

template <bool OUT_HALF, bool BIAS>
__device__ __forceinline__ void gemm_core_h(
    const __half* __restrict__ A, const __half* __restrict__ Bt,
    void* __restrict__ Cv, const float* __restrict__ bias,
    int Kd, int ldc, int rt, int ct, char* sm)
{
    const uint32_t sb = smem_u32(sm);
    const int tid  = threadIdx.x;
    const int lane = tid & 31;
    const int w    = tid >> 5;
    const int wm   = w >> 1;
    const int wn   = w & 1;
    const int g    = lane >> 2;
    const int tg   = lane & 3;

    // ldmatrix bases (stage-relative)
    const uint32_t aA = sb + ((((wm * 64 + (lane & 15)) * LDKH2)
                               + ((lane >> 4) << 3)) << 1);
    const uint32_t aB = sb + (128 * LDKH2 * 2)
                        + ((((wn * 64 + (lane & 15)) * LDKH2)
                            + ((lane >> 4) << 3)) << 1);

    // staging: thread -> A row tid, B row tid; 4 cp16 each (64B)
    const __half* gA = A  + (size_t)(rt * 128 + tid) * Kd;
    const __half* gB = Bt + (size_t)(ct * 128 + tid) * Kd;
    const uint32_t stA = sb + ((tid * LDKH2) << 1);
    const uint32_t stB = sb + (128 * LDKH2 * 2) + ((tid * LDKH2) << 1);

    float acc[4][8][4];
#pragma unroll
    for (int i = 0; i < 4; i++)
#pragma unroll
        for (int j = 0; j < 8; j++)
#pragma unroll
            for (int t = 0; t < 4; t++) acc[i][j][t] = 0.f;

    const int T = Kd >> 5;   // chunks of 32 halfs

    // prologue: chunks 0,1 -> stages 0,1
#pragma unroll
    for (int s = 0; s < 2; s++) {
        const uint32_t so = s * HSTG2_B;
        const int k0 = s << 5;
#pragma unroll
        for (int c = 0; c < 4; c++) {
            cp16(stA + so + (c << 4), gA + k0 + c * 8);
            cp16(stB + so + (c << 4), gB + k0 + c * 8);
        }
        asm volatile("cp.async.commit_group;\n");
    }

    int bc = 0;   // compute buffer  = t % 3
    int bp = 2;   // prefetch buffer = (t+2) % 3
    for (int t = 0; t < T; t++) {
        if (t + 1 < T) asm volatile("cp.async.wait_group 1;\n");
        else           asm volatile("cp.async.wait_group 0;\n");
        __syncthreads();

        if (t + 2 < T) {
            const uint32_t so2 = bp * HSTG2_B;
            const int k0 = (t + 2) << 5;
#pragma unroll
            for (int c = 0; c < 4; c++) {
                cp16(stA + so2 + (c << 4), gA + k0 + c * 8);
                cp16(stB + so2 + (c << 4), gB + k0 + c * 8);
            }
            asm volatile("cp.async.commit_group;\n");
        }

        const uint32_t so = bc * HSTG2_B;
#pragma unroll
        for (int kk = 0; kk < 2; kk++) {
            const uint32_t ko = so + kk * 32;   // 16 halfs
            uint32_t a[4][4], b[8][2];
#pragma unroll
            for (int mi = 0; mi < 4; mi++)
                ldsm4(a[mi][0], a[mi][1], a[mi][2], a[mi][3],
                      aA + ko + mi * (16 * LDKH2 * 2));
#pragma unroll
            for (int p = 0; p < 4; p++) {
                uint32_t r0, r1, r2, r3;
                ldsm4(r0, r1, r2, r3, aB + ko + p * (16 * LDKH2 * 2));
                b[2 * p][0] = r0; b[2 * p][1] = r2;
                b[2 * p + 1][0] = r1; b[2 * p + 1][1] = r3;
            }
#pragma unroll
            for (int mi = 0; mi < 4; mi++)
#pragma unroll
                for (int ni = 0; ni < 8; ni++)
                    mma_f16(acc[mi][ni], a[mi], b[ni]);
        }
        bc = (bc == 2) ? 0 : bc + 1;
        bp = (bp == 2) ? 0 : bp + 1;
    }

    // epilogue
#pragma unroll
    for (int mi = 0; mi < 4; mi++) {
        const int r0 = rt * 128 + wm * 64 + mi * 16 + g;
#pragma unroll
        for (int ni = 0; ni < 8; ni++) {
            const int c0 = ct * 128 + wn * 64 + ni * 8 + tg * 2;
            if (OUT_HALF) {
                __half* C = (__half*)Cv;
                __half2 v0 = __floats2half2_rn(acc[mi][ni][0], acc[mi][ni][1]);
                __half2 v1 = __floats2half2_rn(acc[mi][ni][2], acc[mi][ni][3]);
                *reinterpret_cast<__half2*>(&C[(size_t)r0 * ldc + c0])       = v0;
                *reinterpret_cast<__half2*>(&C[(size_t)(r0 + 8) * ldc + c0]) = v1;
            } else {
                float* C = (float*)Cv;
                float2 v0 = make_float2(acc[mi][ni][0], acc[mi][ni][1]);
                float2 v1 = make_float2(acc[mi][ni][2], acc[mi][ni][3]);
                if (BIAS) {
                    float b0 = __ldg(&bias[c0]), b1 = __ldg(&bias[c0 + 1]);
                    v0.x += b0; v0.y += b1; v1.x += b0; v1.y += b1;
                }
                *reinterpret_cast<float2*>(&C[(size_t)r0 * ldc + c0])       = v0;
                *reinterpret_cast<float2*>(&C[(size_t)(r0 + 8) * ldc + c0]) = v1;
            }
        }
    }
}

// Fused Q + KV projections: Q 64x4=256 tiles, KV 32x8=256 tiles -> 512 CTAs.
__global__ void __launch_bounds__(128) gemm_qkv_k(
    const __half* __restrict__ xh, const __half* __restrict__ wqt,
    __half* __restrict__ q,
    const __half* __restrict__ ch, const __half* __restrict__ wkvt,
    __half* __restrict__ kv)
{
    extern __shared__ char smc[];
    const int bid = blockIdx.x;
    if (bid < 256) {
        gemm_core_h<true, false>(xh, wqt, q, nullptr, QD_, INNER_,
                                 bid >> 2, bid & 3, smc);
    } else {
        const int b2 = bid - 256;
        gemm_core_h<true, false>(ch, wkvt, kv, nullptr, CD_, KV_LD,
                                 b2 >> 3, b2 & 7, smc);
    }
}

// Output projection: 64 x 8 = 512 CTAs.
__global__ void __launch_bounds__(128) gemm_out_k(
    const __half* __restrict__ o, const __half* __restrict__ wot,
    float* __restrict__ out, const float* __restrict__ bout)
{
    extern __shared__ char smc[];
    const int bid = blockIdx.x;
    gemm_core_h<false, true>(o, wot, out, bout, INNER_, QD_,
                             bid >> 3, bid & 7, smc);
}

// ---------------------------------------------------------------------------
// Fused fp16 flash attention: per CTA one (b,h), 128 q-rows, 8 stages of
// 128 keys (two 64-key softmax subtiles per stage). One sync per stage.
// Smem: Q[128][72]h, K stages 2x[128][72]h, V stages 2x[128][72]h.
// ---------------------------------------------------------------------------
#define LDKH   72
#define FQ_B   (128 * LDKH * 2)          // 18432
#define FT2_B  (128 * LDKH * 2)          // 18432 per K/V stage (128 keys)
#define FLASH_SMEM (FQ_B + 4 * FT2_B)    // 92160

__global__ void __launch_bounds__(256) flash_attn_h(
    const __half* __restrict__ Q, const __half* __restrict__ KV,
    __half* __restrict__ O)
{
    extern __shared__ char smc[];
    const uint32_t sb = smem_u32(smc);

    const int qt = blockIdx.x;
    const int z  = blockIdx.y;
    const int b  = z >> 3, h = z & 7;
    const int tid = threadIdx.x;
    const int wid = tid >> 5;
    const int lane = tid & 31;
    const int g  = lane >> 2;
    const int tg = lane & 3;

    const __half* Qb = Q  + (size_t)b * N_ * INNER_ + h * D_;
    const __half* Kb = KV + (size_t)b * M_ * KV_LD + h * D_;
    const __half* Vb = KV + (size_t)b * M_ * KV_LD + INNER_ + h * D_;

    // per-thread staging coords: 2 threads per 128B row
    const int kr = tid >> 1, kc = (tid & 1) * 32;

    // ---- prologue: Q tile + K/V stage 0 (j0 = 0), one group
    {
#pragma unroll
        for (int i = 0; i < 4; i++)
            cp16(sb + (((kr * LDKH + kc) << 1) + (i << 4)),
                 Qb + (size_t)(qt * 128 + kr) * INNER_ + kc + i * 8);
#pragma unroll
        for (int i = 0; i < 4; i++) {
            cp16(sb + FQ_B + (((kr * LDKH + kc) << 1) + (i << 4)),
                 Kb + (size_t)kr * KV_LD + kc + i * 8);
            cp16(sb + FQ_B + 2 * FT2_B + (((kr * LDKH + kc) << 1) + (i << 4)),
                 Vb + (size_t)kr * KV_LD + kc + i * 8);
        }
        asm volatile("cp.async.commit_group;\n");
    }
    asm volatile("cp.async.wait_group 0;\n");
    __syncthreads();

    // ---- Q fragments (ldmatrix), fold in softmax scale (exact pow2)
    uint32_t aq[4][4];
    {
        const uint32_t qbase = sb + ((((wid * 16 + (lane & 15)) * LDKH)
                                      + ((lane >> 4) << 3)) << 1);
#pragma unroll
        for (int kc2 = 0; kc2 < 4; kc2++)
            ldsm4(aq[kc2][0], aq[kc2][1], aq[kc2][2], aq[kc2][3], qbase + kc2 * 32);
        const __half2 sc = __float2half2_rn(SCALE_);
#pragma unroll
        for (int kc2 = 0; kc2 < 4; kc2++)
#pragma unroll
            for (int i = 0; i < 4; i++) {
                __half2 v = *reinterpret_cast<__half2*>(&aq[kc2][i]);
                v = __hmul2(v, sc);
                aq[kc2][i] = *reinterpret_cast<uint32_t*>(&v);
            }
    }

    float m0 = -1e30f, m1 = -1e30f, l0 = 0.f, l1 = 0.f;
    float o[8][4];
#pragma unroll
    for (int ni = 0; ni < 8; ni++)
#pragma unroll
        for (int t = 0; t < 4; t++) o[ni][t] = 0.f;

    const int sr15 = lane & 15;
    const int sk8  = (lane >> 4) << 3;

    for (int jt = 0; jt < 8; jt++) {
        // prefetch next 128-key stage into the other buffer
        if (jt + 1 < 8) {
            const int st = (jt + 1) & 1;
            const int j0 = (jt + 1) * 128;
#pragma unroll
            for (int i = 0; i < 4; i++) {
                cp16(sb + FQ_B + st * FT2_B + (((kr * LDKH + kc) << 1) + (i << 4)),
                     Kb + (size_t)(j0 + kr) * KV_LD + kc + i * 8);
                cp16(sb + FQ_B + 2 * FT2_B + st * FT2_B
                        + (((kr * LDKH + kc) << 1) + (i << 4)),
                     Vb + (size_t)(j0 + kr) * KV_LD + kc + i * 8);
            }
            asm volatile("cp.async.commit_group;\n");
        }

#pragma unroll
        for (int half = 0; half < 2; half++) {
            const uint32_t ksb = sb + FQ_B + (jt & 1) * FT2_B
                                 + half * (64 * LDKH * 2);
            const uint32_t vsb = sb + FQ_B + 2 * FT2_B + (jt & 1) * FT2_B
                                 + half * (64 * LDKH * 2);

            // ---- S = (scaled Q) K^T
            float s[8][4];
#pragma unroll
            for (int ni = 0; ni < 8; ni++)
#pragma unroll
                for (int t = 0; t < 4; t++) s[ni][t] = 0.f;
#pragma unroll
            for (int kc2 = 0; kc2 < 4; kc2++) {
                uint32_t bk[8][2];
#pragma unroll
                for (int p = 0; p < 4; p++) {
                    uint32_t r0, r1, r2, r3;
                    ldsm4(r0, r1, r2, r3,
                          ksb + ((((p * 16 + sr15) * LDKH) + kc2 * 16 + sk8) << 1));
                    bk[2 * p][0] = r0; bk[2 * p][1] = r2;
                    bk[2 * p + 1][0] = r1; bk[2 * p + 1][1] = r3;
                }
#pragma unroll
                for (int ni = 0; ni < 8; ni++)
                    mma_f16(s[ni], aq[kc2], bk[ni]);
            }

            // ---- online softmax (rows g, g+8)
            float rm0 = -1e30f, rm1 = -1e30f;
#pragma unroll
            for (int ni = 0; ni < 8; ni++) {
                rm0 = fmaxf(rm0, fmaxf(s[ni][0], s[ni][1]));
                rm1 = fmaxf(rm1, fmaxf(s[ni][2], s[ni][3]));
            }
#pragma unroll
            for (int off = 1; off <= 2; off <<= 1) {
                rm0 = fmaxf(rm0, __shfl_xor_sync(~0u, rm0, off));
                rm1 = fmaxf(rm1, __shfl_xor_sync(~0u, rm1, off));
            }
            const float mn0 = fmaxf(m0, rm0), mn1 = fmaxf(m1, rm1);
            const float cf0 = __expf(m0 - mn0), cf1 = __expf(m1 - mn1);

            float rs0 = 0.f, rs1 = 0.f;
#pragma unroll
            for (int ni = 0; ni < 8; ni++) {
                s[ni][0] = __expf(s[ni][0] - mn0);
                s[ni][1] = __expf(s[ni][1] - mn0);
                s[ni][2] = __expf(s[ni][2] - mn1);
                s[ni][3] = __expf(s[ni][3] - mn1);
                rs0 += s[ni][0] + s[ni][1];
                rs1 += s[ni][2] + s[ni][3];
            }
#pragma unroll
            for (int off = 1; off <= 2; off <<= 1) {
                rs0 += __shfl_xor_sync(~0u, rs0, off);
                rs1 += __shfl_xor_sync(~0u, rs1, off);
            }
            l0 = l0 * cf0 + rs0;
            l1 = l1 * cf1 + rs1;
            m0 = mn0; m1 = mn1;
#pragma unroll
            for (int ni = 0; ni < 8; ni++) {
                o[ni][0] *= cf0; o[ni][1] *= cf0;
                o[ni][2] *= cf1; o[ni][3] *= cf1;
            }

            // ---- O += P V : P C-frags reused as A-frags (fp16 identity)
#pragma unroll
            for (int j = 0; j < 4; j++) {
                uint32_t ap[4];
                ap[0] = packh2(s[2 * j][0],     s[2 * j][1]);
                ap[1] = packh2(s[2 * j][2],     s[2 * j][3]);
                ap[2] = packh2(s[2 * j + 1][0], s[2 * j + 1][1]);
                ap[3] = packh2(s[2 * j + 1][2], s[2 * j + 1][3]);
                uint32_t bv[8][2];
#pragma unroll
                for (int p = 0; p < 4; p++) {
                    uint32_t r0, r1, r2, r3;
                    ldsm4t(r0, r1, r2, r3,
                           vsb + ((((j * 16 + sr15) * LDKH) + p * 16 + sk8) << 1));
                    bv[2 * p][0] = r0; bv[2 * p][1] = r1;
                    bv[2 * p + 1][0] = r2; bv[2 * p + 1][1] = r3;
                }
#pragma unroll
                for (int ni = 0; ni < 8; ni++)
                    mma_f16(o[ni], ap, bv[ni]);
            }
        }

        if (jt + 1 < 8) {
            asm volatile("cp.async.wait_group 0;\n");
            __syncthreads();
        }
    }

    // ---- epilogue: normalize, store half
    const float inv0 = 1.0f / l0, inv1 = 1.0f / l1;
    const int r0 = qt * 128 + wid * 16 + g;
    __half* Ob = O + (size_t)b * N_ * INNER_ + h * D_;
#pragma unroll
    for (int ni = 0; ni < 8; ni++) {
        const int c0 = ni * 8 + tg * 2;
        __half2 v0 = __floats2half2_rn(o[ni][0] * inv0, o[ni][1] * inv0);
        __half2 v1 = __floats2half2_rn(o[ni][2] * inv1, o[ni][3] * inv1);
        *reinterpret_cast<__half2*>(&Ob[(size_t)r0 * INNER_ + c0])       = v0;
        *reinterpret_cast<__half2*>(&Ob[(size_t)(r0 + 8) * INNER_ + c0]) = v1;
    }
}

// ---------------------------------------------------------------------------
extern "C" void kernel_launch(void* const* d_in, const int* in_sizes, int n_in,
                              void* d_out, int out_size)
{
    const float* x    = (const float*)d_in[0];
    const float* ctx  = (const float*)d_in[1];
    const float* Wq   = (const float*)d_in[2];
    const float* Wk   = (const float*)d_in[3];
    const float* Wv   = (const float*)d_in[4];
    const float* Wout = (const float*)d_in[5];
    const float* bout = (const float*)d_in[6];
    float* out = (float*)d_out;

    __half *xh, *ch, *wqt, *wkvt, *wot, *q, *kv, *o;
    cudaGetSymbolAddress((void**)&xh,   g_xh);
    cudaGetSymbolAddress((void**)&ch,   g_ch);
    cudaGetSymbolAddress((void**)&wqt,  g_wqt);
    cudaGetSymbolAddress((void**)&wkvt, g_wkvt);
    cudaGetSymbolAddress((void**)&wot,  g_wot);
    cudaGetSymbolAddress((void**)&q,    g_q);
    cudaGetSymbolAddress((void**)&kv,   g_kv);
    cudaGetSymbolAddress((void**)&o,    g_o);

    cudaFuncSetAttribute(gemm_qkv_k,
                         cudaFuncAttributeMaxDynamicSharedMemorySize, GEMM_SMEM);
    cudaFuncSetAttribute(gemm_out_k,
                         cudaFuncAttributeMaxDynamicSharedMemorySize, GEMM_SMEM);
    cudaFuncSetAttribute(flash_attn_h,
                         cudaFuncAttributeMaxDynamicSharedMemorySize, FLASH_SMEM);

    // ---- prep
    {
        const int n4x = B_ * N_ * QD_ / 4;
        const int n4c = B_ * M_ * CD_ / 4;
        round_copy2h_k<<<(n4x + n4c + 255) / 256, 256>>>(
            (const float4*)x, (uint2*)xh, n4x,
            (const float4*)ctx, (uint2*)ch, n4c);
        transpose_round4h_k<<<dim3(32, 32, 4), 256>>>(
            Wq, wqt, Wk, wkvt, Wv, wkvt + (size_t)INNER_ * CD_, Wout, wot);
    }

    // ---- fused Q + K|V projections (512 CTAs)
    gemm_qkv_k<<<512, 128, GEMM_SMEM>>>(xh, wqt, q, ch, wkvt, kv);

    // ---- fused attention
    flash_attn_h<<<dim3(16, 32), 256, FLASH_SMEM>>>(q, kv, o);

    // ---- output projection (+bias)
    gemm_out_k<<<512, 128, GEMM_SMEM>>>(o, wot, out, bout);
}

// round 11
// speedup vs baseline: 1.0359x; 1.0359x over previous
#include <cuda_runtime.h>
#include <cuda_fp16.h>
#include <cstdint>

// ---------------------------------------------------------------------------
// CrossAttention, fp16-operand / fp32-accum pipeline (m16n8k16 HMMA).
// GEMMs: BK=32, 3-stage cp.async (2-ahead prefetch), 64x64 warp tiles.
// Flash: 64-key stages, 3-stage cp.async (2-tile lookahead), 1 sync/tile.
// b=4, n=2048, m=1024, qd=1024, cd=768, heads=8, dim_head=64, inner=512
// ---------------------------------------------------------------------------

#define B_     4
#define N_     2048
#define M_     1024
#define QD_    1024
#define CD_    768
#define H_     8
#define D_     64
#define INNER_ 512
#define KV_LD  1024
#define SCALE_ 0.125f   // 64^-0.5 (exact power of two)

// Scratch (device globals: allocation-free rule)
__device__ __align__(16) static __half g_xh[(size_t)B_ * N_ * QD_];
__device__ __align__(16) static __half g_ch[(size_t)B_ * M_ * CD_];
__device__ __align__(16) static __half g_wqt[(size_t)INNER_ * QD_];
__device__ __align__(16) static __half g_wkvt[(size_t)KV_LD * CD_];   // [Wk^T; Wv^T]
__device__ __align__(16) static __half g_wot[(size_t)QD_ * INNER_];
__device__ __align__(16) static __half g_q[(size_t)B_ * N_ * INNER_];
__device__ __align__(16) static __half g_kv[(size_t)B_ * M_ * KV_LD]; // K | V
__device__ __align__(16) static __half g_o[(size_t)B_ * N_ * INNER_];

__device__ __forceinline__ uint32_t smem_u32(const void* p) {
    return (uint32_t)__cvta_generic_to_shared(p);
}
__device__ __forceinline__ void cp16(uint32_t saddr, const void* g) {
    asm volatile("cp.async.cg.shared.global [%0], [%1], 16;\n" :: "r"(saddr), "l"(g));
}
__device__ __forceinline__ void ldsm4(uint32_t& r0, uint32_t& r1, uint32_t& r2,
                                      uint32_t& r3, uint32_t addr) {
    asm volatile("ldmatrix.sync.aligned.m8n8.x4.shared.b16 {%0,%1,%2,%3}, [%4];"
                 : "=r"(r0), "=r"(r1), "=r"(r2), "=r"(r3) : "r"(addr));
}
__device__ __forceinline__ void ldsm4t(uint32_t& r0, uint32_t& r1, uint32_t& r2,
                                       uint32_t& r3, uint32_t addr) {
    asm volatile("ldmatrix.sync.aligned.m8n8.x4.trans.shared.b16 {%0,%1,%2,%3}, [%4];"
                 : "=r"(r0), "=r"(r1), "=r"(r2), "=r"(r3) : "r"(addr));
}
__device__ __forceinline__ void mma_f16(float c[4], const uint32_t a[4],
                                        const uint32_t b[2]) {
    asm volatile(
        "mma.sync.aligned.m16n8k16.row.col.f32.f16.f16.f32 "
        "{%0,%1,%2,%3}, {%4,%5,%6,%7}, {%8,%9}, {%0,%1,%2,%3};\n"
        : "+f"(c[0]), "+f"(c[1]), "+f"(c[2]), "+f"(c[3])
        : "r"(a[0]), "r"(a[1]), "r"(a[2]), "r"(a[3]), "r"(b[0]), "r"(b[1]));
}
__device__ __forceinline__ uint32_t packh2(float lo, float hi) {
    __half2 h = __floats2half2_rn(lo, hi);
    return *reinterpret_cast<uint32_t*>(&h);
}

// ---------------------------------------------------------------------------
// Prep: fp16-round copies (x, ctx) and 4-way transpose+round (weights).
// ---------------------------------------------------------------------------
__global__ void __launch_bounds__(256) round_copy2h_k(
    const float4* __restrict__ a, uint2* __restrict__ ao, int n4a,
    const float4* __restrict__ b, uint2* __restrict__ bo, int n4b)
{
    int i = blockIdx.x * 256 + threadIdx.x;
    if (i < n4a) {
        float4 t = a[i];
        uint2 r; r.x = packh2(t.x, t.y); r.y = packh2(t.z, t.w);
        ao[i] = r;
    } else if (i < n4a + n4b) {
        int j = i - n4a;
        float4 t = b[j];
        uint2 r; r.x = packh2(t.x, t.y); r.y = packh2(t.z, t.w);
        bo[j] = r;
    }
}

__global__ void __launch_bounds__(256) transpose_round4h_k(
    const float* __restrict__ W0, __half* __restrict__ T0,
    const float* __restrict__ W1, __half* __restrict__ T1,
    const float* __restrict__ W2, __half* __restrict__ T2,
    const float* __restrict__ W3, __half* __restrict__ T3)
{
    const float* W; __half* Tt; int K, N;
    switch (blockIdx.z) {
        case 0:  W = W0; Tt = T0; K = QD_;    N = INNER_; break;
        case 1:  W = W1; Tt = T1; K = CD_;    N = INNER_; break;
        case 2:  W = W2; Tt = T2; K = CD_;    N = INNER_; break;
        default: W = W3; Tt = T3; K = INNER_; N = QD_;    break;
    }
    const int n0 = blockIdx.x * 32, k0 = blockIdx.y * 32;
    if (n0 >= N || k0 >= K) return;

    __shared__ float t[32][33];
    const int tx = threadIdx.x & 31, ty = threadIdx.x >> 5;
#pragma unroll
    for (int j = 0; j < 32; j += 8)
        t[ty + j][tx] = W[(long)(k0 + ty + j) * N + n0 + tx];
    __syncthreads();
#pragma unroll
    for (int j = 0; j < 32; j += 8)
        Tt[(long)(n0 + ty + j) * K + k0 + tx] = __float2half_rn(t[tx][ty + j]);
}

// ---------------------------------------------------------------------------
// fp16 GEMM core (round-10 config): C[128x128 tile] = A[M][K] * Bt[N][K]^T.
// 4 warps (64x64 each), BK=32 halfs, 3-stage cp.async (prefetch 2 ahead),
// one __syncthreads per chunk. Rows padded to 40 halfs (80B).
// ---------------------------------------------------------------------------
#define LDKH2   40
#define HSTG2_B ((128 + 128) * LDKH2 * 2)   // 20480 B per stage
#define GEMM_SMEM (3 * HSTG2_B)             // 61440 B

template <bool OUT_HALF, bool BIAS>
__device__ __forceinline__ void gemm_core_h(
    const __half* __restrict__ A, const __half* __restrict__ Bt,
    void* __restrict__ Cv, const float* __restrict__ bias,
    int Kd, int ldc, int rt, int ct, char* sm)
{
    const uint32_t sb = smem_u32(sm);
    const int tid  = threadIdx.x;
    const int lane = tid & 31;
    const int w    = tid >> 5;
    const int wm   = w >> 1;
    const int wn   = w & 1;
    const int g    = lane >> 2;
    const int tg   = lane & 3;

    const uint32_t aA = sb + ((((wm * 64 + (lane & 15)) * LDKH2)
                               + ((lane >> 4) << 3)) << 1);
    const uint32_t aB = sb + (128 * LDKH2 * 2)
                        + ((((wn * 64 + (lane & 15)) * LDKH2)
                            + ((lane >> 4) << 3)) << 1);

    const __half* gA = A  + (size_t)(rt * 128 + tid) * Kd;
    const __half* gB = Bt + (size_t)(ct * 128 + tid) * Kd;
    const uint32_t stA = sb + ((tid * LDKH2) << 1);
    const uint32_t stB = sb + (128 * LDKH2 * 2) + ((tid * LDKH2) << 1);

    float acc[4][8][4];
#pragma unroll
    for (int i = 0; i < 4; i++)
#pragma unroll
        for (int j = 0; j < 8; j++)
#pragma unroll
            for (int t = 0; t < 4; t++) acc[i][j][t] = 0.f;

    const int T = Kd >> 5;

#pragma unroll
    for (int s = 0; s < 2; s++) {
        const uint32_t so = s * HSTG2_B;
        const int k0 = s << 5;
#pragma unroll
        for (int c = 0; c < 4; c++) {
            cp16(stA + so + (c << 4), gA + k0 + c * 8);
            cp16(stB + so + (c << 4), gB + k0 + c * 8);
        }
        asm volatile("cp.async.commit_group;\n");
    }

    int bc = 0, bp = 2;
    for (int t = 0; t < T; t++) {
        if (t + 1 < T) asm volatile("cp.async.wait_group 1;\n");
        else           asm volatile("cp.async.wait_group 0;\n");
        __syncthreads();

        if (t + 2 < T) {
            const uint32_t so2 = bp * HSTG2_B;
            const int k0 = (t + 2) << 5;
#pragma unroll
            for (int c = 0; c < 4; c++) {
                cp16(stA + so2 + (c << 4), gA + k0 + c * 8);
                cp16(stB + so2 + (c << 4), gB + k0 + c * 8);
            }
            asm volatile("cp.async.commit_group;\n");
        }

        const uint32_t so = bc * HSTG2_B;
#pragma unroll
        for (int kk = 0; kk < 2; kk++) {
            const uint32_t ko = so + kk * 32;
            uint32_t a[4][4], b[8][2];
#pragma unroll
            for (int mi = 0; mi < 4; mi++)
                ldsm4(a[mi][0], a[mi][1], a[mi][2], a[mi][3],
                      aA + ko + mi * (16 * LDKH2 * 2));
#pragma unroll
            for (int p = 0; p < 4; p++) {
                uint32_t r0, r1, r2, r3;
                ldsm4(r0, r1, r2, r3, aB + ko + p * (16 * LDKH2 * 2));
                b[2 * p][0] = r0; b[2 * p][1] = r2;
                b[2 * p + 1][0] = r1; b[2 * p + 1][1] = r3;
            }
#pragma unroll
            for (int mi = 0; mi < 4; mi++)
#pragma unroll
                for (int ni = 0; ni < 8; ni++)
                    mma_f16(acc[mi][ni], a[mi], b[ni]);
        }
        bc = (bc == 2) ? 0 : bc + 1;
        bp = (bp == 2) ? 0 : bp + 1;
    }

#pragma unroll
    for (int mi = 0; mi < 4; mi++) {
        const int r0 = rt * 128 + wm * 64 + mi * 16 + g;
#pragma unroll
        for (int ni = 0; ni < 8; ni++) {
            const int c0 = ct * 128 + wn * 64 + ni * 8 + tg * 2;
            if (OUT_HALF) {
                __half* C = (__half*)Cv;
                __half2 v0 = __floats2half2_rn(acc[mi][ni][0], acc[mi][ni][1]);
                __half2 v1 = __floats2half2_rn(acc[mi][ni][2], acc[mi][ni][3]);
                *reinterpret_cast<__half2*>(&C[(size_t)r0 * ldc + c0])       = v0;
                *reinterpret_cast<__half2*>(&C[(size_t)(r0 + 8) * ldc + c0]) = v1;
            } else {
                float* C = (float*)Cv;
                float2 v0 = make_float2(acc[mi][ni][0], acc[mi][ni][1]);
                float2 v1 = make_float2(acc[mi][ni][2], acc[mi][ni][3]);
                if (BIAS) {
                    float b0 = __ldg(&bias[c0]), b1 = __ldg(&bias[c0 + 1]);
                    v0.x += b0; v0.y += b1; v1.x += b0; v1.y += b1;
                }
                *reinterpret_cast<float2*>(&C[(size_t)r0 * ldc + c0])       = v0;
                *reinterpret_cast<float2*>(&C[(size_t)(r0 + 8) * ldc + c0]) = v1;
            }
        }
    }
}

__global__ void __launch_bounds__(128) gemm_qkv_k(
    const __half* __restrict__ xh, const __half* __restrict__ wqt,
    __half* __restrict__ q,
    const __half* __restrict__ ch, const __half* __restrict__ wkvt,
    __half* __restrict__ kv)
{
    extern __shared__ char smc[];
    const int bid = blockIdx.x;
    if (bid < 256) {
        gemm_core_h<true, false>(xh, wqt, q, nullptr, QD_, INNER_,
                                 bid >> 2, bid & 3, smc);
    } else {
        const int b2 = bid - 256;
        gemm_core_h<true, false>(ch, wkvt, kv, nullptr, CD_, KV_LD,
                                 b2 >> 3, b2 & 7, smc);
    }
}

__global__ void __launch_bounds__(128) gemm_out_k(
    const __half* __restrict__ o, const __half* __restrict__ wot,
    float* __restrict__ out, const float* __restrict__ bout)
{
    extern __shared__ char smc[];
    const int bid = blockIdx.x;
    gemm_core_h<false, true>(o, wot, out, bout, INNER_, QD_,
                             bid >> 3, bid & 7, smc);
}

// ---------------------------------------------------------------------------
// Fused fp16 flash attention: per CTA one (b,h), 128 q-rows, 16 key-tiles
// of 64. 3-stage cp.async K/V staging (2-tile lookahead), one sync per tile.
// Smem: Q[128][72]h, K stages 3x[64][72]h, V stages 3x[64][72]h.
// ---------------------------------------------------------------------------
#define LDKH   72
#define FQ_B   (128 * LDKH * 2)          // 18432
#define FT_B   (64 * LDKH * 2)           // 9216 per K/V stage
#define FLASH_SMEM (FQ_B + 6 * FT_B)     // 73728

__global__ void __launch_bounds__(256) flash_attn_h(
    const __half* __restrict__ Q, const __half* __restrict__ KV,
    __half* __restrict__ O)
{
    extern __shared__ char smc[];
    const uint32_t sb = smem_u32(smc);

    const int qt = blockIdx.x;
    const int z  = blockIdx.y;
    const int b  = z >> 3, h = z & 7;
    const int tid = threadIdx.x;
    const int wid = tid >> 5;
    const int lane = tid & 31;
    const int g  = lane >> 2;
    const int tg = lane & 3;

    const __half* Qb = Q  + (size_t)b * N_ * INNER_ + h * D_;
    const __half* Kb = KV + (size_t)b * M_ * KV_LD + h * D_;
    const __half* Vb = KV + (size_t)b * M_ * KV_LD + INNER_ + h * D_;

    // staging coords: K/V 4 threads per row (16 halfs each)
    const int kr = tid >> 2, kc = (tid & 3) * 16;

    // ---- prologue: group0 = Q + tile0, group1 = tile1
    {
        const int qr = tid >> 1, qc = (tid & 1) * 32;
#pragma unroll
        for (int i = 0; i < 4; i++)
            cp16(sb + (((qr * LDKH + qc) << 1) + (i << 4)),
                 Qb + (size_t)(qt * 128 + qr) * INNER_ + qc + i * 8);
#pragma unroll
        for (int i = 0; i < 2; i++) {
            cp16(sb + FQ_B + (((kr * LDKH + kc) << 1) + (i << 4)),
                 Kb + (size_t)kr * KV_LD + kc + i * 8);
            cp16(sb + FQ_B + 3 * FT_B + (((kr * LDKH + kc) << 1) + (i << 4)),
                 Vb + (size_t)kr * KV_LD + kc + i * 8);
        }
        asm volatile("cp.async.commit_group;\n");
#pragma unroll
        for (int i = 0; i < 2; i++) {
            cp16(sb + FQ_B + FT_B + (((kr * LDKH + kc) << 1) + (i << 4)),
                 Kb + (size_t)(64 + kr) * KV_LD + kc + i * 8);
            cp16(sb + FQ_B + 3 * FT_B + FT_B + (((kr * LDKH + kc) << 1) + (i << 4)),
                 Vb + (size_t)(64 + kr) * KV_LD + kc + i * 8);
        }
        asm volatile("cp.async.commit_group;\n");
    }
    asm volatile("cp.async.wait_group 1;\n");   // Q + tile0 ready
    __syncthreads();

    // ---- Q fragments (ldmatrix), fold in softmax scale (exact pow2)
    uint32_t aq[4][4];
    {
        const uint32_t qbase = sb + ((((wid * 16 + (lane & 15)) * LDKH)
                                      + ((lane >> 4) << 3)) << 1);
#pragma unroll
        for (int kc2 = 0; kc2 < 4; kc2++)
            ldsm4(aq[kc2][0], aq[kc2][1], aq[kc2][2], aq[kc2][3], qbase + kc2 * 32);
        const __half2 sc = __float2half2_rn(SCALE_);
#pragma unroll
        for (int kc2 = 0; kc2 < 4; kc2++)
#pragma unroll
            for (int i = 0; i < 4; i++) {
                __half2 v = *reinterpret_cast<__half2*>(&aq[kc2][i]);
                v = __hmul2(v, sc);
                aq[kc2][i] = *reinterpret_cast<uint32_t*>(&v);
            }
    }

    float m0 = -1e30f, m1 = -1e30f, l0 = 0.f, l1 = 0.f;
    float o[8][4];
#pragma unroll
    for (int ni = 0; ni < 8; ni++)
#pragma unroll
        for (int t = 0; t < 4; t++) o[ni][t] = 0.f;

    const int sr15 = lane & 15;
    const int sk8  = (lane >> 4) << 3;

    int bc = 0, bp = 2;   // compute buf = jt%3, prefetch buf = (jt+2)%3
    for (int jt = 0; jt < 16; jt++) {
        // prefetch tile jt+2 into buffer bp (read at iter jt-1, sync'd)
        if (jt + 2 < 16) {
            const int j0 = (jt + 2) * 64;
#pragma unroll
            for (int i = 0; i < 2; i++) {
                cp16(sb + FQ_B + bp * FT_B + (((kr * LDKH + kc) << 1) + (i << 4)),
                     Kb + (size_t)(j0 + kr) * KV_LD + kc + i * 8);
                cp16(sb + FQ_B + 3 * FT_B + bp * FT_B
                        + (((kr * LDKH + kc) << 1) + (i << 4)),
                     Vb + (size_t)(j0 + kr) * KV_LD + kc + i * 8);
            }
            asm volatile("cp.async.commit_group;\n");
        }

        const uint32_t ksb = sb + FQ_B + bc * FT_B;
        const uint32_t vsb = sb + FQ_B + 3 * FT_B + bc * FT_B;

        // ---- S = (scaled Q) K^T
        float s[8][4];
#pragma unroll
        for (int ni = 0; ni < 8; ni++)
#pragma unroll
            for (int t = 0; t < 4; t++) s[ni][t] = 0.f;
#pragma unroll
        for (int kc2 = 0; kc2 < 4; kc2++) {
            uint32_t bk[8][2];
#pragma unroll
            for (int p = 0; p < 4; p++) {
                uint32_t r0, r1, r2, r3;
                ldsm4(r0, r1, r2, r3,
                      ksb + ((((p * 16 + sr15) * LDKH) + kc2 * 16 + sk8) << 1));
                bk[2 * p][0] = r0; bk[2 * p][1] = r2;
                bk[2 * p + 1][0] = r1; bk[2 * p + 1][1] = r3;
            }
#pragma unroll
            for (int ni = 0; ni < 8; ni++)
                mma_f16(s[ni], aq[kc2], bk[ni]);
        }

        // ---- online softmax (rows g, g+8)
        float rm0 = -1e30f, rm1 = -1e30f;
#pragma unroll
        for (int ni = 0; ni < 8; ni++) {
            rm0 = fmaxf(rm0, fmaxf(s[ni][0], s[ni][1]));
            rm1 = fmaxf(rm1, fmaxf(s[ni][2], s[ni][3]));
        }
#pragma unroll
        for (int off = 1; off <= 2; off <<= 1) {
            rm0 = fmaxf(rm0, __shfl_xor_sync(~0u, rm0, off));
            rm1 = fmaxf(rm1, __shfl_xor_sync(~0u, rm1, off));
        }
        const float mn0 = fmaxf(m0, rm0), mn1 = fmaxf(m1, rm1);
        const float cf0 = __expf(m0 - mn0), cf1 = __expf(m1 - mn1);

        float rs0 = 0.f, rs1 = 0.f;
#pragma unroll
        for (int ni = 0; ni < 8; ni++) {
            s[ni][0] = __expf(s[ni][0] - mn0);
            s[ni][1] = __expf(s[ni][1] - mn0);
            s[ni][2] = __expf(s[ni][2] - mn1);
            s[ni][3] = __expf(s[ni][3] - mn1);
            rs0 += s[ni][0] + s[ni][1];
            rs1 += s[ni][2] + s[ni][3];
        }
#pragma unroll
        for (int off = 1; off <= 2; off <<= 1) {
            rs0 += __shfl_xor_sync(~0u, rs0, off);
            rs1 += __shfl_xor_sync(~0u, rs1, off);
        }
        l0 = l0 * cf0 + rs0;
        l1 = l1 * cf1 + rs1;
        m0 = mn0; m1 = mn1;
#pragma unroll
        for (int ni = 0; ni < 8; ni++) {
            o[ni][0] *= cf0; o[ni][1] *= cf0;
            o[ni][2] *= cf1; o[ni][3] *= cf1;
        }

        // ---- O += P V : P C-frags reused as A-frags (fp16 identity)
#pragma unroll
        for (int j = 0; j < 4; j++) {
            uint32_t ap[4];
            ap[0] = packh2(s[2 * j][0],     s[2 * j][1]);
            ap[1] = packh2(s[2 * j][2],     s[2 * j][3]);
            ap[2] = packh2(s[2 * j + 1][0], s[2 * j + 1][1]);
            ap[3] = packh2(s[2 * j + 1][2], s[2 * j + 1][3]);
            uint32_t bv[8][2];
#pragma unroll
            for (int p = 0; p < 4; p++) {
                uint32_t r0, r1, r2, r3;
                ldsm4t(r0, r1, r2, r3,
                       vsb + ((((j * 16 + sr15) * LDKH) + p * 16 + sk8) << 1));
                bv[2 * p][0] = r0; bv[2 * p][1] = r1;
                bv[2 * p + 1][0] = r2; bv[2 * p + 1][1] = r3;
            }
#pragma unroll
            for (int ni = 0; ni < 8; ni++)
                mma_f16(o[ni], ap, bv[ni]);
        }

        if (jt + 1 < 16) {
            if (jt + 2 < 16) asm volatile("cp.async.wait_group 1;\n");
            else             asm volatile("cp.async.wait_group 0;\n");
            __syncthreads();
        }
        bc = (bc == 2) ? 0 : bc + 1;
        bp = (bp == 2) ? 0 : bp + 1;
    }

    // ---- epilogue: normalize, store half
    const float inv0 = 1.0f / l0, inv1 = 1.0f / l1;
    const int r0 = qt * 128 + wid * 16 + g;
    __half* Ob = O + (size_t)b * N_ * INNER_ + h * D_;
#pragma unroll
    for (int ni = 0; ni < 8; ni++) {
        const int c0 = ni * 8 + tg * 2;
        __half2 v0 = __floats2half2_rn(o[ni][0] * inv0, o[ni][1] * inv0);
        __half2 v1 = __floats2half2_rn(o[ni][2] * inv1, o[ni][3] * inv1);
        *reinterpret_cast<__half2*>(&Ob[(size_t)r0 * INNER_ + c0])       = v0;
        *reinterpret_cast<__half2*>(&Ob[(size_t)(r0 + 8) * INNER_ + c0]) = v1;
    }
}

// ---------------------------------------------------------------------------
extern "C" void kernel_launch(void* const* d_in, const int* in_sizes, int n_in,
                              void* d_out, int out_size)
{
    const float* x    = (const float*)d_in[0];
    const float* ctx  = (const float*)d_in[1];
    const float* Wq   = (const float*)d_in[2];
    const float* Wk   = (const float*)d_in[3];
    const float* Wv   = (const float*)d_in[4];
    const float* Wout = (const float*)d_in[5];
    const float* bout = (const float*)d_in[6];
    float* out = (float*)d_out;

    __half *xh, *ch, *wqt, *wkvt, *wot, *q, *kv, *o;
    cudaGetSymbolAddress((void**)&xh,   g_xh);
    cudaGetSymbolAddress((void**)&ch,   g_ch);
    cudaGetSymbolAddress((void**)&wqt,  g_wqt);
    cudaGetSymbolAddress((void**)&wkvt, g_wkvt);
    cudaGetSymbolAddress((void**)&wot,  g_wot);
    cudaGetSymbolAddress((void**)&q,    g_q);
    cudaGetSymbolAddress((void**)&kv,   g_kv);
    cudaGetSymbolAddress((void**)&o,    g_o);

    cudaFuncSetAttribute(gemm_qkv_k,
                         cudaFuncAttributeMaxDynamicSharedMemorySize, GEMM_SMEM);
    cudaFuncSetAttribute(gemm_out_k,
                         cudaFuncAttributeMaxDynamicSharedMemorySize, GEMM_SMEM);
    cudaFuncSetAttribute(flash_attn_h,
                         cudaFuncAttributeMaxDynamicSharedMemorySize, FLASH_SMEM);

    // ---- prep
    {
        const int n4x = B_ * N_ * QD_ / 4;
        const int n4c = B_ * M_ * CD_ / 4;
        round_copy2h_k<<<(n4x + n4c + 255) / 256, 256>>>(
            (const float4*)x, (uint2*)xh, n4x,
            (const float4*)ctx, (uint2*)ch, n4c);
        transpose_round4h_k<<<dim3(32, 32, 4), 256>>>(
            Wq, wqt, Wk, wkvt, Wv, wkvt + (size_t)INNER_ * CD_, Wout, wot);
    }

    // ---- fused Q + K|V projections (512 CTAs)
    gemm_qkv_k<<<512, 128, GEMM_SMEM>>>(xh, wqt, q, ch, wkvt, kv);

    // ---- fused attention
    flash_attn_h<<<dim3(16, 32), 256, FLASH_SMEM>>>(q, kv, o);

    // ---- output projection (+bias)
    gemm_out_k<<<512, 128, GEMM_SMEM>>>(o, wot, out, bout);
}